// round 6
// baseline (speedup 1.0000x reference)
#include <cuda_runtime.h>
#include <cuda_bf16.h>
#include <math_constants.h>

// Problem constants (shapes fixed by the dataset)
#define NN 50000
#define EE 1600000
#define FDIM 128
#define DENC 32
#define DEMB 12
#define DOUT 44   // DENC + DEMB fused outputs
#define DH 128

// -------- device scratch (static: no allocation allowed) --------
__device__ float g_s[NN];          // s[i] = relu(enc[i]) . w_inf[0:32]
__device__ float g_inf[NN];        // influence logits (base written by encode, edges atomically added)
__device__ float g_emb[NN * DEMB]; // emb[i] = nodes[i] @ W_emb + b_emb
__device__ float g_pmax[128];      // partial maxes
__device__ float g_maxval;         // global max of influence
__device__ float g_accum[13];      // [0:12] = sum w*emb, [12] = sum w

// -------- packed f32x2 helpers --------
__device__ __forceinline__ unsigned long long pack2(float lo, float hi) {
    unsigned long long r;
    asm("mov.b64 %0, {%1, %2};" : "=l"(r) : "r"(__float_as_uint(lo)), "r"(__float_as_uint(hi)));
    return r;
}
__device__ __forceinline__ unsigned long long ffma2(unsigned long long a, unsigned long long b,
                                                    unsigned long long c) {
    unsigned long long d;
    asm("fma.rn.f32x2 %0, %1, %2, %3;" : "=l"(d) : "l"(a), "l"(b), "l"(c));
    return d;
}
__device__ __forceinline__ float lo32(unsigned long long v) { return __uint_as_float((unsigned)(v & 0xFFFFFFFFull)); }
__device__ __forceinline__ float hi32(unsigned long long v) { return __uint_as_float((unsigned)(v >> 32)); }

// ============================================================================
// Kernel A: fused encode. Per thread: 2 nodes, 44 packed accumulators.
//   enc = relu(x @ W_enc + b_enc); s = enc . w_inf; inf0 = s + x[127]*w_inf[32] + b_inf
//   emb = x @ W_emb + b_emb
// ============================================================================
__global__ __launch_bounds__(64) void encode_kernel(
    const float* __restrict__ nodes,
    const float* __restrict__ W_enc, const float* __restrict__ b_enc,
    const float* __restrict__ W_inf, const float* __restrict__ b_inf,
    const float* __restrict__ W_emb, const float* __restrict__ b_emb,
    int n)
{
    __shared__ unsigned long long Wp[FDIM * DOUT];  // weights duplicated into both f32x2 halves
    __shared__ float sh_winf[33];
    __shared__ float sh_b[DOUT];
    __shared__ float sh_binf;

    const int tid = threadIdx.x;
    for (int idx = tid; idx < FDIM * DOUT; idx += blockDim.x) {
        int k = idx / DOUT, j = idx % DOUT;
        float w = (j < DENC) ? W_enc[k * DENC + j] : W_emb[k * DEMB + (j - DENC)];
        unsigned int u = __float_as_uint(w);
        Wp[idx] = ((unsigned long long)u << 32) | u;
    }
    if (tid < 33) sh_winf[tid] = W_inf[tid];
    if (tid < DENC) sh_b[tid] = b_enc[tid];
    if (tid >= DENC && tid < DOUT) sh_b[tid] = b_emb[tid - DENC];
    if (tid == 0) sh_binf = b_inf[0];
    __syncthreads();

    const int base = blockIdx.x * (2 * blockDim.x);
    const int i0 = base + tid;
    const int i1 = base + blockDim.x + tid;
    const bool v0 = (i0 < n), v1 = (i1 < n);
    const float4* r0 = (const float4*)(nodes + (v0 ? (long)i0 * FDIM : 0));
    const float4* r1 = (const float4*)(nodes + (v1 ? (long)i1 * FDIM : 0));

    unsigned long long acc[DOUT];
#pragma unroll
    for (int j = 0; j < DOUT; j++) acc[j] = 0ull;

    float4 a = r0[0], b4 = r1[0];
    float last0 = 0.f, last1 = 0.f;
#pragma unroll 1
    for (int c = 0; c < FDIM / 4; c++) {
        float4 an, bn;
        if (c < FDIM / 4 - 1) { an = r0[c + 1]; bn = r1[c + 1]; }
        unsigned long long x0 = pack2(a.x, b4.x);
        unsigned long long x1 = pack2(a.y, b4.y);
        unsigned long long x2 = pack2(a.z, b4.z);
        unsigned long long x3 = pack2(a.w, b4.w);
        const unsigned long long* w0 = &Wp[(4 * c + 0) * DOUT];
        const unsigned long long* w1 = &Wp[(4 * c + 1) * DOUT];
        const unsigned long long* w2 = &Wp[(4 * c + 2) * DOUT];
        const unsigned long long* w3 = &Wp[(4 * c + 3) * DOUT];
#pragma unroll
        for (int j = 0; j < DOUT; j++) {
            unsigned long long t = acc[j];
            t = ffma2(x0, w0[j], t);
            t = ffma2(x1, w1[j], t);
            t = ffma2(x2, w2[j], t);
            t = ffma2(x3, w3[j], t);
            acc[j] = t;
        }
        if (c == FDIM / 4 - 1) { last0 = a.w; last1 = b4.w; }
        a = an; b4 = bn;
    }

    // epilogue: relu enc, dot with w_inf; emb raw
    float s0 = 0.f, s1 = 0.f;
    float e0j[DENC], e1j[DENC];
#pragma unroll
    for (int j = 0; j < DENC; j++) {
        e0j[j] = fmaxf(lo32(acc[j]) + sh_b[j], 0.f);
        e1j[j] = fmaxf(hi32(acc[j]) + sh_b[j], 0.f);
        s0 += e0j[j] * sh_winf[j];
        s1 += e1j[j] * sh_winf[j];
    }
    if (v0) {
        g_s[i0] = s0;
        g_inf[i0] = s0 + last0 * sh_winf[32] + sh_binf;
        float4* ep = (float4*)(g_emb + (long)i0 * DEMB);
        float4 u;
        u.x = lo32(acc[32]) + sh_b[32]; u.y = lo32(acc[33]) + sh_b[33];
        u.z = lo32(acc[34]) + sh_b[34]; u.w = lo32(acc[35]) + sh_b[35]; ep[0] = u;
        u.x = lo32(acc[36]) + sh_b[36]; u.y = lo32(acc[37]) + sh_b[37];
        u.z = lo32(acc[38]) + sh_b[38]; u.w = lo32(acc[39]) + sh_b[39]; ep[1] = u;
        u.x = lo32(acc[40]) + sh_b[40]; u.y = lo32(acc[41]) + sh_b[41];
        u.z = lo32(acc[42]) + sh_b[42]; u.w = lo32(acc[43]) + sh_b[43]; ep[2] = u;
    }
    if (v1) {
        g_s[i1] = s1;
        g_inf[i1] = s1 + last1 * sh_winf[32] + sh_binf;
        float4* ep = (float4*)(g_emb + (long)i1 * DEMB);
        float4 u;
        u.x = hi32(acc[32]) + sh_b[32]; u.y = hi32(acc[33]) + sh_b[33];
        u.z = hi32(acc[34]) + sh_b[34]; u.w = hi32(acc[35]) + sh_b[35]; ep[0] = u;
        u.x = hi32(acc[36]) + sh_b[36]; u.y = hi32(acc[37]) + sh_b[37];
        u.z = hi32(acc[38]) + sh_b[38]; u.w = hi32(acc[39]) + sh_b[39]; ep[1] = u;
        u.x = hi32(acc[40]) + sh_b[40]; u.y = hi32(acc[41]) + sh_b[41];
        u.z = hi32(acc[42]) + sh_b[42]; u.w = hi32(acc[43]) + sh_b[43]; ep[2] = u;
    }
}

// ============================================================================
// Kernel B: scalar edge scatter: inf[recv] += s[snd]
// ============================================================================
__global__ void scatter_kernel(const int* __restrict__ snd, const int* __restrict__ rcv, int e)
{
    int t = blockIdx.x * blockDim.x + threadIdx.x;
    int base = t * 4;
    if (base + 3 < e) {
        int4 aa = *(const int4*)(snd + base);
        int4 bb = *(const int4*)(rcv + base);
        atomicAdd(&g_inf[bb.x], g_s[aa.x]);
        atomicAdd(&g_inf[bb.y], g_s[aa.y]);
        atomicAdd(&g_inf[bb.z], g_s[aa.z]);
        atomicAdd(&g_inf[bb.w], g_s[aa.w]);
    } else {
        for (int i = base; i < e; i++) atomicAdd(&g_inf[rcv[i]], g_s[snd[i]]);
    }
}

// ============================================================================
// Kernel C1: partial max of influence
// ============================================================================
__global__ void max_kernel(int n)
{
    int stride = gridDim.x * blockDim.x;
    float m = -CUDART_INF_F;
    for (int i = blockIdx.x * blockDim.x + threadIdx.x; i < n; i += stride)
        m = fmaxf(m, g_inf[i]);
#pragma unroll
    for (int o = 16; o; o >>= 1) m = fmaxf(m, __shfl_xor_sync(0xFFFFFFFFu, m, o));
    __shared__ float wm[8];
    if ((threadIdx.x & 31) == 0) wm[threadIdx.x >> 5] = m;
    __syncthreads();
    if (threadIdx.x == 0) {
        float mm = wm[0];
        for (int w = 1; w < (int)(blockDim.x >> 5); w++) mm = fmaxf(mm, wm[w]);
        g_pmax[blockIdx.x] = mm;
    }
}

// Kernel C2: finish max, zero accumulators
__global__ void finalize_max_kernel(int nb)
{
    int t = threadIdx.x;
    float m = (t < nb) ? g_pmax[t] : -CUDART_INF_F;
#pragma unroll
    for (int o = 16; o; o >>= 1) m = fmaxf(m, __shfl_xor_sync(0xFFFFFFFFu, m, o));
    __shared__ float wm[4];
    if ((t & 31) == 0) wm[t >> 5] = m;
    __syncthreads();
    if (t == 0) {
        float mm = fmaxf(fmaxf(wm[0], wm[1]), fmaxf(wm[2], wm[3]));
        g_maxval = mm;
    }
    if (t < 13) g_accum[t] = 0.f;
}

// ============================================================================
// Kernel D: softmax-weighted pooling: accum[j] = sum_i e^{inf_i - max} * emb[i][j], accum[12] = sum e^
// ============================================================================
__global__ void pool_kernel(int n)
{
    const float gm = g_maxval;
    int stride = gridDim.x * blockDim.x;
    float sw = 0.f;
    float gc[DEMB];
#pragma unroll
    for (int j = 0; j < DEMB; j++) gc[j] = 0.f;

    for (int i = blockIdx.x * blockDim.x + threadIdx.x; i < n; i += stride) {
        float w = __expf(g_inf[i] - gm);
        sw += w;
        const float4* ep = (const float4*)(g_emb + (long)i * DEMB);
        float4 e0 = ep[0], e1 = ep[1], e2 = ep[2];
        gc[0] += w * e0.x; gc[1] += w * e0.y; gc[2]  += w * e0.z; gc[3]  += w * e0.w;
        gc[4] += w * e1.x; gc[5] += w * e1.y; gc[6]  += w * e1.z; gc[7]  += w * e1.w;
        gc[8] += w * e2.x; gc[9] += w * e2.y; gc[10] += w * e2.z; gc[11] += w * e2.w;
    }
#pragma unroll
    for (int o = 16; o; o >>= 1) {
        sw += __shfl_xor_sync(0xFFFFFFFFu, sw, o);
#pragma unroll
        for (int j = 0; j < DEMB; j++) gc[j] += __shfl_xor_sync(0xFFFFFFFFu, gc[j], o);
    }
    if ((threadIdx.x & 31) == 0) {
        atomicAdd(&g_accum[12], sw);
#pragma unroll
        for (int j = 0; j < DEMB; j++) atomicAdd(&g_accum[j], gc[j]);
    }
}

// ============================================================================
// Kernel E: head MLP (single block, 128 threads)
// ============================================================================
__global__ __launch_bounds__(DH) void head_kernel(
    const float* __restrict__ W1, const float* __restrict__ b1,
    const float* __restrict__ W2, const float* __restrict__ b2,
    const float* __restrict__ Wy, const float* __restrict__ by,
    const float* __restrict__ Wx, const float* __restrict__ bx,
    float* __restrict__ out)
{
    __shared__ float g[DEMB];
    __shared__ float h1[DH];
    __shared__ float h2[DH];
    const int t = threadIdx.x;
    const float sw = g_accum[12];
    if (t < DEMB) g[t] = g_accum[t] / sw;
    __syncthreads();

    float a = b1[t];
#pragma unroll
    for (int j = 0; j < DEMB; j++) a += g[j] * W1[j * DH + t];
    h1[t] = fmaxf(a, 0.f);
    __syncthreads();

    float c = b2[t];
#pragma unroll 8
    for (int k = 0; k < DH; k++) c += h1[k] * W2[k * DH + t];
    h2[t] = fmaxf(c, 0.f);
    __syncthreads();

    if (t < 4) {
        float o = bx[t];
        for (int k = 0; k < DH; k++) o += h2[k] * Wx[k * 4 + t];
        out[t] = o / 10.0f;
    }
    if (t == 4) {
        float o = by[0];
        for (int k = 0; k < DH; k++) o += h2[k] * Wy[k];
        out[4] = o;
    }
}

// ============================================================================
extern "C" void kernel_launch(void* const* d_in, const int* in_sizes, int n_in,
                              void* d_out, int out_size)
{
    const float* nodes  = (const float*)d_in[0];
    const int*   snd    = (const int*)d_in[1];
    const int*   rcv    = (const int*)d_in[2];
    const float* W_enc  = (const float*)d_in[3];
    const float* b_enc  = (const float*)d_in[4];
    const float* W_inf  = (const float*)d_in[5];
    const float* b_inf  = (const float*)d_in[6];
    const float* W_emb  = (const float*)d_in[7];
    const float* b_emb  = (const float*)d_in[8];
    const float* W1     = (const float*)d_in[9];
    const float* b1     = (const float*)d_in[10];
    const float* W2     = (const float*)d_in[11];
    const float* b2     = (const float*)d_in[12];
    const float* Wy     = (const float*)d_in[13];
    const float* by     = (const float*)d_in[14];
    const float* Wx     = (const float*)d_in[15];
    const float* bx     = (const float*)d_in[16];
    float* out = (float*)d_out;

    const int n = in_sizes[0] / FDIM;   // 50000
    const int e = in_sizes[1];          // 1600000

    // A: encode (2 nodes / thread, 64-thread blocks -> 128 nodes / block)
    int blocksA = (n + 127) / 128;
    encode_kernel<<<blocksA, 64>>>(nodes, W_enc, b_enc, W_inf, b_inf, W_emb, b_emb, n);

    // B: edge scatter (4 edges / thread)
    int threadsB = (e + 3) / 4;
    int blocksB = (threadsB + 255) / 256;
    scatter_kernel<<<blocksB, 256>>>(snd, rcv, e);

    // C: max reduce
    const int NB1 = 120;
    max_kernel<<<NB1, 256>>>(n);
    finalize_max_kernel<<<1, 128>>>(NB1);

    // D: softmax pooling
    pool_kernel<<<232, 256>>>(n);

    // E: head
    head_kernel<<<1, DH>>>(W1, b1, W2, b2, Wy, by, Wx, bx, out);
}

// round 7
// speedup vs baseline: 1.1270x; 1.1270x over previous
#include <cuda_runtime.h>
#include <cuda_bf16.h>
#include <math_constants.h>

// Problem constants (shapes fixed by the dataset)
#define NN 50000
#define EE 1600000
#define FDIM 128
#define DENC 32
#define DEMB 12
#define NPAIR 22   // 44 fused output cols (32 enc + 12 emb), packed 2 per f32x2
#define DH 128

// -------- device scratch (static: no allocation allowed) --------
__device__ float  g_s[NN];           // s[i] = relu(enc[i]) . w_inf[0:32]
__device__ float  g_inf[NN];         // influence logits
__device__ float  g_emb[NN * DEMB];  // emb[i] = nodes[i] @ W_emb + b_emb
__device__ double d_accum[13];       // [0:12] = sum w*emb, [12] = sum w (double, no max needed)
__device__ unsigned g_done;          // last-block counter for pool_head

// -------- packed f32x2 helpers --------
__device__ __forceinline__ unsigned long long pack2(float lo, float hi) {
    unsigned long long r;
    asm("mov.b64 %0, {%1, %2};" : "=l"(r) : "r"(__float_as_uint(lo)), "r"(__float_as_uint(hi)));
    return r;
}
__device__ __forceinline__ unsigned long long ffma2(unsigned long long a, unsigned long long b,
                                                    unsigned long long c) {
    unsigned long long d;
    asm("fma.rn.f32x2 %0, %1, %2, %3;" : "=l"(d) : "l"(a), "l"(b), "l"(c));
    return d;
}
__device__ __forceinline__ float lo32(unsigned long long v) { return __uint_as_float((unsigned)(v & 0xFFFFFFFFull)); }
__device__ __forceinline__ float hi32(unsigned long long v) { return __uint_as_float((unsigned)(v >> 32)); }

// ============================================================================
// Kernel A: fused encode. One node per thread, 22 packed accumulators where
// each f32x2 holds a PAIR of output columns (2j, 2j+1). x is broadcast into
// both halves; weight pairs are contiguous in row-major W -> real data pairs.
//   enc = relu(x @ W_enc + b_enc); s = enc . w_inf[0:32]
//   inf = s + x[127]*w_inf[32] + b_inf;  emb = x @ W_emb + b_emb
// Also resets d_accum / g_done for this replay (block 0).
// ============================================================================
__global__ __launch_bounds__(256) void encode_kernel(
    const float* __restrict__ nodes,
    const float* __restrict__ W_enc, const float* __restrict__ b_enc,
    const float* __restrict__ W_inf, const float* __restrict__ b_inf,
    const float* __restrict__ W_emb, const float* __restrict__ b_emb,
    int n)
{
    __shared__ __align__(16) unsigned long long Wp[FDIM * NPAIR]; // [k][jpair] = (w_2j | w_2j+1<<32)
    __shared__ float sh_winf[33];
    __shared__ float sh_be[DENC];
    __shared__ float sh_bemb[DEMB];
    __shared__ float sh_binf;

    const int tid = threadIdx.x;

    // per-replay reset of pooling accumulators (stream-ordered before pool_head)
    if (blockIdx.x == 0) {
        if (tid < 13) d_accum[tid] = 0.0;
        if (tid == 13) g_done = 0u;
    }

    for (int idx = tid; idx < FDIM * NPAIR; idx += blockDim.x) {
        int k = idx / NPAIR, j = idx % NPAIR;
        int c0 = 2 * j, c1 = 2 * j + 1;
        float w0 = (c0 < DENC) ? W_enc[k * DENC + c0] : W_emb[k * DEMB + (c0 - DENC)];
        float w1 = (c1 < DENC) ? W_enc[k * DENC + c1] : W_emb[k * DEMB + (c1 - DENC)];
        Wp[idx] = ((unsigned long long)__float_as_uint(w1) << 32) | __float_as_uint(w0);
    }
    if (tid < 33) sh_winf[tid] = W_inf[tid];
    if (tid < DENC) sh_be[tid] = b_enc[tid];
    if (tid < DEMB) sh_bemb[tid] = b_emb[tid];
    if (tid == 0) sh_binf = b_inf[0];
    __syncthreads();

    const int i = blockIdx.x * blockDim.x + tid;
    if (i >= n) return;

    const float4* r = (const float4*)(nodes + (long)i * FDIM);

    unsigned long long acc[NPAIR];
#pragma unroll
    for (int j = 0; j < NPAIR; j++) acc[j] = 0ull;

    float4 a = r[0];
    float last = 0.f;
#pragma unroll 1
    for (int c = 0; c < FDIM / 4; c++) {
        float4 an;
        if (c < FDIM / 4 - 1) an = r[c + 1];
#pragma unroll
        for (int q = 0; q < 4; q++) {
            float v = (q == 0) ? a.x : (q == 1) ? a.y : (q == 2) ? a.z : a.w;
            unsigned long long xp = pack2(v, v);
            const ulonglong2* w2 = (const ulonglong2*)&Wp[(4 * c + q) * NPAIR];
#pragma unroll
            for (int j = 0; j < NPAIR / 2; j++) {
                ulonglong2 ww = w2[j];
                acc[2 * j]     = ffma2(xp, ww.x, acc[2 * j]);
                acc[2 * j + 1] = ffma2(xp, ww.y, acc[2 * j + 1]);
            }
        }
        if (c == FDIM / 4 - 1) last = a.w;
        a = an;
    }

    // epilogue: relu enc pairs, dot with w_inf
    float s = 0.f;
#pragma unroll
    for (int j = 0; j < DENC / 2; j++) {
        float lo = fmaxf(lo32(acc[j]) + sh_be[2 * j],     0.f);
        float hi = fmaxf(hi32(acc[j]) + sh_be[2 * j + 1], 0.f);
        s = fmaf(lo, sh_winf[2 * j],     s);
        s = fmaf(hi, sh_winf[2 * j + 1], s);
    }
    g_s[i]   = s;
    g_inf[i] = s + last * sh_winf[32] + sh_binf;

    // emb = acc[16..21] halves + bias
    float4* ep = (float4*)(g_emb + (long)i * DEMB);
    float4 u;
    u.x = lo32(acc[16]) + sh_bemb[0]; u.y = hi32(acc[16]) + sh_bemb[1];
    u.z = lo32(acc[17]) + sh_bemb[2]; u.w = hi32(acc[17]) + sh_bemb[3]; ep[0] = u;
    u.x = lo32(acc[18]) + sh_bemb[4]; u.y = hi32(acc[18]) + sh_bemb[5];
    u.z = lo32(acc[19]) + sh_bemb[6]; u.w = hi32(acc[19]) + sh_bemb[7]; ep[1] = u;
    u.x = lo32(acc[20]) + sh_bemb[8]; u.y = hi32(acc[20]) + sh_bemb[9];
    u.z = lo32(acc[21]) + sh_bemb[10]; u.w = hi32(acc[21]) + sh_bemb[11]; ep[2] = u;
}

// ============================================================================
// Kernel B: scalar edge scatter: inf[recv] += s[snd]  (4 edges / thread)
// ============================================================================
__global__ void scatter_kernel(const int* __restrict__ snd, const int* __restrict__ rcv, int e)
{
    int t = blockIdx.x * blockDim.x + threadIdx.x;
    int base = t * 4;
    if (base + 3 < e) {
        int4 aa = *(const int4*)(snd + base);
        int4 bb = *(const int4*)(rcv + base);
        atomicAdd(&g_inf[bb.x], g_s[aa.x]);
        atomicAdd(&g_inf[bb.y], g_s[aa.y]);
        atomicAdd(&g_inf[bb.z], g_s[aa.z]);
        atomicAdd(&g_inf[bb.w], g_s[aa.w]);
    } else {
        for (int i = base; i < e; i++) atomicAdd(&g_inf[rcv[i]], g_s[snd[i]]);
    }
}

// ============================================================================
// Kernel C: fused softmax pooling (double, no max pass needed: softmax is
// scale-invariant and double exp() can't overflow here) + head MLP in the
// last block to finish.
// ============================================================================
__global__ __launch_bounds__(256) void pool_head_kernel(
    const float* __restrict__ W1, const float* __restrict__ b1,
    const float* __restrict__ W2, const float* __restrict__ b2,
    const float* __restrict__ Wy, const float* __restrict__ by,
    const float* __restrict__ Wx, const float* __restrict__ bx,
    float* __restrict__ out, int n)
{
    __shared__ double red[8][13];
    __shared__ double flag_and_g[16];   // [0] = last-block flag; [1..13] = accum snapshot
    __shared__ float h1[DH], h2[DH];

    const int t = threadIdx.x;
    const int stride = gridDim.x * blockDim.x;

    double sw = 0.0;
    double gc[DEMB];
#pragma unroll
    for (int j = 0; j < DEMB; j++) gc[j] = 0.0;

    for (int i = blockIdx.x * blockDim.x + t; i < n; i += stride) {
        double e = exp((double)g_inf[i]);
        const float4* ep = (const float4*)(g_emb + (long)i * DEMB);
        float4 e0 = ep[0], e1 = ep[1], e2 = ep[2];
        sw += e;
        gc[0]  = fma(e, (double)e0.x, gc[0]);  gc[1]  = fma(e, (double)e0.y, gc[1]);
        gc[2]  = fma(e, (double)e0.z, gc[2]);  gc[3]  = fma(e, (double)e0.w, gc[3]);
        gc[4]  = fma(e, (double)e1.x, gc[4]);  gc[5]  = fma(e, (double)e1.y, gc[5]);
        gc[6]  = fma(e, (double)e1.z, gc[6]);  gc[7]  = fma(e, (double)e1.w, gc[7]);
        gc[8]  = fma(e, (double)e2.x, gc[8]);  gc[9]  = fma(e, (double)e2.y, gc[9]);
        gc[10] = fma(e, (double)e2.z, gc[10]); gc[11] = fma(e, (double)e2.w, gc[11]);
    }
#pragma unroll
    for (int o = 16; o; o >>= 1) {
        sw += __shfl_xor_sync(0xFFFFFFFFu, sw, o);
#pragma unroll
        for (int j = 0; j < DEMB; j++) gc[j] += __shfl_xor_sync(0xFFFFFFFFu, gc[j], o);
    }
    const int w = t >> 5, l = t & 31;
    if (l == 0) {
#pragma unroll
        for (int j = 0; j < DEMB; j++) red[w][j] = gc[j];
        red[w][12] = sw;
    }
    __syncthreads();
    if (t == 0) {
        for (int ww = 1; ww < 8; ww++)
            for (int j = 0; j < 13; j++) red[0][j] += red[ww][j];
        for (int j = 0; j < 13; j++) atomicAdd(&d_accum[j], red[0][j]);
        __threadfence();
        unsigned done = atomicAdd(&g_done, 1u);
        flag_and_g[0] = (done == gridDim.x - 1) ? 1.0 : 0.0;
    }
    __syncthreads();
    if (flag_and_g[0] == 0.0) return;

    // ---- last block: head MLP ----
    __threadfence();
    if (t < 13) flag_and_g[1 + t] = atomicAdd(&d_accum[t], 0.0);  // coherent read
    __syncthreads();
    // g[j] = accum[j] / accum[12]
    if (t < DH) {
        float a = b1[t];
#pragma unroll
        for (int j = 0; j < DEMB; j++) {
            float gj = (float)(flag_and_g[1 + j] / flag_and_g[13]);
            a = fmaf(gj, W1[j * DH + t], a);
        }
        h1[t] = fmaxf(a, 0.f);
    }
    __syncthreads();
    if (t < DH) {
        float c = b2[t];
#pragma unroll 8
        for (int k = 0; k < DH; k++) c = fmaf(h1[k], W2[k * DH + t], c);
        h2[t] = fmaxf(c, 0.f);
    }
    __syncthreads();
    if (t < 4) {
        float o = bx[t];
        for (int k = 0; k < DH; k++) o = fmaf(h2[k], Wx[k * 4 + t], o);
        out[t] = o / 10.0f;
    }
    if (t == 4) {
        float o = by[0];
        for (int k = 0; k < DH; k++) o = fmaf(h2[k], Wy[k], o);
        out[4] = o;
    }
}

// ============================================================================
extern "C" void kernel_launch(void* const* d_in, const int* in_sizes, int n_in,
                              void* d_out, int out_size)
{
    const float* nodes  = (const float*)d_in[0];
    const int*   snd    = (const int*)d_in[1];
    const int*   rcv    = (const int*)d_in[2];
    const float* W_enc  = (const float*)d_in[3];
    const float* b_enc  = (const float*)d_in[4];
    const float* W_inf  = (const float*)d_in[5];
    const float* b_inf  = (const float*)d_in[6];
    const float* W_emb  = (const float*)d_in[7];
    const float* b_emb  = (const float*)d_in[8];
    const float* W1     = (const float*)d_in[9];
    const float* b1     = (const float*)d_in[10];
    const float* W2     = (const float*)d_in[11];
    const float* b2     = (const float*)d_in[12];
    const float* Wy     = (const float*)d_in[13];
    const float* by     = (const float*)d_in[14];
    const float* Wx     = (const float*)d_in[15];
    const float* bx     = (const float*)d_in[16];
    float* out = (float*)d_out;

    const int n = in_sizes[0] / FDIM;   // 50000
    const int e = in_sizes[1];          // 1600000

    // A: encode, one node / thread
    int blocksA = (n + 255) / 256;
    encode_kernel<<<blocksA, 256>>>(nodes, W_enc, b_enc, W_inf, b_inf, W_emb, b_emb, n);

    // B: edge scatter (4 edges / thread)
    int threadsB = (e + 3) / 4;
    int blocksB = (threadsB + 255) / 256;
    scatter_kernel<<<blocksB, 256>>>(snd, rcv, e);

    // C: softmax pooling + head (last block finishes)
    pool_head_kernel<<<148, 256>>>(W1, b1, W2, b2, Wy, by, Wx, bx, out, n);
}

// round 8
// speedup vs baseline: 1.3128x; 1.1648x over previous
#include <cuda_runtime.h>
#include <cuda_bf16.h>
#include <math_constants.h>

// Problem constants (shapes fixed by the dataset)
#define NN 50000
#define EE 1600000
#define FDIM 128
#define DENC 32
#define DEMB 12
#define NP24 24    // 48 fused output cols (32 enc + 12 emb + 4 pad), 2 per f32x2 pair
#define DH 128
#define FIN_GRID 148

// -------- device scratch (static: no allocation allowed) --------
__device__ float    g_s[NN];            // s[i] = relu(enc[i]) . w_inf[0:32]
__device__ float    g_inf[NN];          // influence logits
__device__ float    g_emb[NN * DEMB];   // emb[i] = nodes[i] @ W_emb + b_emb
__device__ float    g_part[FIN_GRID * 13]; // per-block pooling partials (deterministic)
__device__ unsigned g_bar1, g_bar2, g_done, g_maxu;

// -------- packed f32x2 helpers --------
__device__ __forceinline__ unsigned long long pack2(float lo, float hi) {
    unsigned long long r;
    asm("mov.b64 %0, {%1, %2};" : "=l"(r) : "r"(__float_as_uint(lo)), "r"(__float_as_uint(hi)));
    return r;
}
__device__ __forceinline__ unsigned long long ffma2(unsigned long long a, unsigned long long b,
                                                    unsigned long long c) {
    unsigned long long d;
    asm("fma.rn.f32x2 %0, %1, %2, %3;" : "=l"(d) : "l"(a), "l"(b), "l"(c));
    return d;
}
__device__ __forceinline__ float lo32(unsigned long long v) { return __uint_as_float((unsigned)(v & 0xFFFFFFFFull)); }
__device__ __forceinline__ float hi32(unsigned long long v) { return __uint_as_float((unsigned)(v >> 32)); }

// ordered-float <-> uint for atomicMax
__device__ __forceinline__ unsigned fl_enc(float x) {
    unsigned b = __float_as_uint(x);
    return (b & 0x80000000u) ? ~b : (b | 0x80000000u);
}
__device__ __forceinline__ float fl_dec(unsigned u) {
    unsigned b = (u & 0x80000000u) ? (u ^ 0x80000000u) : ~u;
    return __uint_as_float(b);
}

// ============================================================================
// Kernel A: fused encode. 2 nodes x 6 column-pairs per thread (4-way column
// split). 256 thr/block: colg = tid&3 owns pairs [6*colg, 6*colg+6);
// nsub = tid>>2 picks nodes (base+nsub, base+64+nsub). Biases folded into
// accumulator init. Weight LDS.128 shared by 8 lanes; node LDG shared by 4.
// ============================================================================
__global__ __launch_bounds__(256) void encode_kernel(
    const float* __restrict__ nodes,
    const float* __restrict__ W_enc,
    const float* __restrict__ b_enc,
    const float* __restrict__ W_inf, const float* __restrict__ b_inf,
    const float* __restrict__ W_emb,
    const float* __restrict__ b_emb,
    int n)
{
    __shared__ __align__(16) unsigned long long Wp[FDIM * NP24]; // [k][jpair]
    __shared__ unsigned long long bpair[NP24];
    __shared__ float sh_winf[33];
    __shared__ float sh_binf;
    __shared__ float s_sh[64 * 8];   // [nsub][node(2)][colg(4)]

    const int tid = threadIdx.x;

    // per-replay reset of finish-kernel state (stream-ordered before finish)
    if (blockIdx.x == 0 && tid < 4) {
        if (tid == 0) g_bar1 = 0u;
        if (tid == 1) g_bar2 = 0u;
        if (tid == 2) g_done = 0u;
        if (tid == 3) g_maxu = 0u;
    }

    for (int idx = tid; idx < FDIM * NP24; idx += 256) {
        int k = idx / NP24, j = idx % NP24;
        int c0 = 2 * j, c1 = 2 * j + 1;
        float w0 = (c0 < DENC) ? W_enc[k * DENC + c0]
                 : (c0 < DENC + DEMB) ? W_emb[k * DEMB + (c0 - DENC)] : 0.f;
        float w1 = (c1 < DENC) ? W_enc[k * DENC + c1]
                 : (c1 < DENC + DEMB) ? W_emb[k * DEMB + (c1 - DENC)] : 0.f;
        Wp[idx] = ((unsigned long long)__float_as_uint(w1) << 32) | __float_as_uint(w0);
    }
    if (tid < NP24) {
        int c0 = 2 * tid, c1 = 2 * tid + 1;
        float v0 = (c0 < DENC) ? b_enc[c0] : (c0 < DENC + DEMB) ? b_emb[c0 - DENC] : 0.f;
        float v1 = (c1 < DENC) ? b_enc[c1] : (c1 < DENC + DEMB) ? b_emb[c1 - DENC] : 0.f;
        bpair[tid] = ((unsigned long long)__float_as_uint(v1) << 32) | __float_as_uint(v0);
    }
    if (tid < 33) sh_winf[tid] = W_inf[tid];
    if (tid == 0) sh_binf = b_inf[0];
    __syncthreads();

    const int colg = tid & 3;
    const int nsub = tid >> 2;
    const int base = blockIdx.x * 128;
    const int i0 = base + nsub;
    const int i1 = base + 64 + nsub;
    const bool v0 = (i0 < n), v1 = (i1 < n);
    const float4* r0 = (const float4*)(nodes + (v0 ? (size_t)i0 * FDIM : 0));
    const float4* r1 = (const float4*)(nodes + (v1 ? (size_t)i1 * FDIM : 0));
    const int jg = 6 * colg;

    unsigned long long acc0[6], acc1[6];
#pragma unroll
    for (int p = 0; p < 6; p++) { acc0[p] = bpair[jg + p]; acc1[p] = bpair[jg + p]; }

    float4 a0 = r0[0], a1 = r1[0];
    float last0 = 0.f, last1 = 0.f;
#pragma unroll 1
    for (int c = 0; c < FDIM / 4; c++) {
        float4 p0, p1;
        if (c < FDIM / 4 - 1) { p0 = r0[c + 1]; p1 = r1[c + 1]; }
#pragma unroll
        for (int q = 0; q < 4; q++) {
            float f0 = (q == 0) ? a0.x : (q == 1) ? a0.y : (q == 2) ? a0.z : a0.w;
            float f1 = (q == 0) ? a1.x : (q == 1) ? a1.y : (q == 2) ? a1.z : a1.w;
            unsigned long long x0 = pack2(f0, f0);
            unsigned long long x1 = pack2(f1, f1);
            const ulonglong2* w2 = (const ulonglong2*)&Wp[(4 * c + q) * NP24 + jg];
            ulonglong2 wa = w2[0], wb = w2[1], wc = w2[2];
            acc0[0] = ffma2(x0, wa.x, acc0[0]); acc1[0] = ffma2(x1, wa.x, acc1[0]);
            acc0[1] = ffma2(x0, wa.y, acc0[1]); acc1[1] = ffma2(x1, wa.y, acc1[1]);
            acc0[2] = ffma2(x0, wb.x, acc0[2]); acc1[2] = ffma2(x1, wb.x, acc1[2]);
            acc0[3] = ffma2(x0, wb.y, acc0[3]); acc1[3] = ffma2(x1, wb.y, acc1[3]);
            acc0[4] = ffma2(x0, wc.x, acc0[4]); acc1[4] = ffma2(x1, wc.x, acc1[4]);
            acc0[5] = ffma2(x0, wc.y, acc0[5]); acc1[5] = ffma2(x1, wc.y, acc1[5]);
        }
        if (c == FDIM / 4 - 1) { last0 = a0.w; last1 = a1.w; }
        a0 = p0; a1 = p1;
    }

    // partial s over enc pairs (j < 16); bias already in acc
    float s0 = 0.f, s1 = 0.f;
#pragma unroll
    for (int p = 0; p < 6; p++) {
        int j = jg + p;
        if (j < 16) {
            float wl = sh_winf[2 * j], wh = sh_winf[2 * j + 1];
            s0 = fmaf(fmaxf(lo32(acc0[p]), 0.f), wl, s0);
            s0 = fmaf(fmaxf(hi32(acc0[p]), 0.f), wh, s0);
            s1 = fmaf(fmaxf(lo32(acc1[p]), 0.f), wl, s1);
            s1 = fmaf(fmaxf(hi32(acc1[p]), 0.f), wh, s1);
        }
    }
    s_sh[nsub * 8 + colg]     = s0;
    s_sh[nsub * 8 + 4 + colg] = s1;
    __syncthreads();

    if (colg == 0 && v0) {
        float s = s_sh[nsub * 8 + 0] + s_sh[nsub * 8 + 1] + s_sh[nsub * 8 + 2] + s_sh[nsub * 8 + 3];
        g_s[i0] = s;
        g_inf[i0] = s + last0 * sh_winf[32] + sh_binf;
    }
    if (colg == 1 && v1) {
        float s = s_sh[nsub * 8 + 4] + s_sh[nsub * 8 + 5] + s_sh[nsub * 8 + 6] + s_sh[nsub * 8 + 7];
        g_s[i1] = s;
        g_inf[i1] = s + last1 * sh_winf[32] + sh_binf;
    }
    // emb: colg2 holds pairs j16,j17 (emb cols 0-3); colg3 holds j18..21 (cols 4-11)
    if (colg == 2) {
        float4 u; u.x = lo32(acc0[4]); u.y = hi32(acc0[4]); u.z = lo32(acc0[5]); u.w = hi32(acc0[5]);
        if (v0) ((float4*)(g_emb + (size_t)i0 * DEMB))[0] = u;
        u.x = lo32(acc1[4]); u.y = hi32(acc1[4]); u.z = lo32(acc1[5]); u.w = hi32(acc1[5]);
        if (v1) ((float4*)(g_emb + (size_t)i1 * DEMB))[0] = u;
    }
    if (colg == 3) {
        float4 u;
        if (v0) {
            float4* ep = (float4*)(g_emb + (size_t)i0 * DEMB);
            u.x = lo32(acc0[0]); u.y = hi32(acc0[0]); u.z = lo32(acc0[1]); u.w = hi32(acc0[1]); ep[1] = u;
            u.x = lo32(acc0[2]); u.y = hi32(acc0[2]); u.z = lo32(acc0[3]); u.w = hi32(acc0[3]); ep[2] = u;
        }
        if (v1) {
            float4* ep = (float4*)(g_emb + (size_t)i1 * DEMB);
            u.x = lo32(acc1[0]); u.y = hi32(acc1[0]); u.z = lo32(acc1[1]); u.w = hi32(acc1[1]); ep[1] = u;
            u.x = lo32(acc1[2]); u.y = hi32(acc1[2]); u.z = lo32(acc1[3]); u.w = hi32(acc1[3]); ep[2] = u;
        }
    }
}

// ============================================================================
// Kernel B: persistent fused finish. grid = 148 (all co-resident, 1st wave):
//   phase 1: edge scatter inf[recv] += s[snd]   (REDG, fire-and-forget)
//   barrier 1 (counter spin)
//   phase 2: global max of inf (atomicMax on ordered-uint)
//   barrier 2
//   phase 3: float softmax pooling -> deterministic per-block partials
//   last block: sum partials + head MLP
// ============================================================================
__global__ __launch_bounds__(256) void finish_kernel(
    const int* __restrict__ snd, const int* __restrict__ rcv,
    const float* __restrict__ W1, const float* __restrict__ b1,
    const float* __restrict__ W2, const float* __restrict__ b2,
    const float* __restrict__ Wy, const float* __restrict__ by,
    const float* __restrict__ Wx, const float* __restrict__ bx,
    float* __restrict__ out, int n, int e)
{
    __shared__ float red[8][13];
    __shared__ float sh_misc[16];   // [0]=last-block flag; [1..13]=summed accum
    __shared__ float h1[DH], h2[DH];

    const int t = threadIdx.x;
    const int gtid = blockIdx.x * 256 + t;
    const int gstride = gridDim.x * 256;

    // ---- phase 1: scatter (4 edges / iteration) ----
    const int nq = e >> 2;
    for (int q = gtid; q < nq; q += gstride) {
        int4 aa = ((const int4*)snd)[q];
        int4 bb = ((const int4*)rcv)[q];
        atomicAdd(&g_inf[bb.x], g_s[aa.x]);
        atomicAdd(&g_inf[bb.y], g_s[aa.y]);
        atomicAdd(&g_inf[bb.z], g_s[aa.z]);
        atomicAdd(&g_inf[bb.w], g_s[aa.w]);
    }
    for (int i = (nq << 2) + gtid; i < e; i += gstride)
        atomicAdd(&g_inf[rcv[i]], g_s[snd[i]]);

    __threadfence();
    if (t == 0) {
        atomicAdd(&g_bar1, 1u);
        while (*(volatile unsigned*)&g_bar1 < gridDim.x) { }
    }
    __syncthreads();

    // ---- phase 2: max ----
    float m = -CUDART_INF_F;
    for (int i = gtid; i < n; i += gstride) m = fmaxf(m, g_inf[i]);
#pragma unroll
    for (int o = 16; o; o >>= 1) m = fmaxf(m, __shfl_xor_sync(0xFFFFFFFFu, m, o));
    if ((t & 31) == 0) red[t >> 5][0] = m;
    __syncthreads();
    if (t == 0) {
        float mm = red[0][0];
        for (int w = 1; w < 8; w++) mm = fmaxf(mm, red[w][0]);
        atomicMax(&g_maxu, fl_enc(mm));
        __threadfence();
        atomicAdd(&g_bar2, 1u);
        while (*(volatile unsigned*)&g_bar2 < gridDim.x) { }
        sh_misc[15] = fl_dec(*(volatile unsigned*)&g_maxu);
    }
    __syncthreads();
    const float gm = sh_misc[15];

    // ---- phase 3: float softmax pooling ----
    float sw = 0.f;
    float gc[DEMB];
#pragma unroll
    for (int j = 0; j < DEMB; j++) gc[j] = 0.f;
    for (int i = gtid; i < n; i += gstride) {
        float w = __expf(g_inf[i] - gm);
        const float4* ep = (const float4*)(g_emb + (size_t)i * DEMB);
        float4 e0 = ep[0], e1 = ep[1], e2 = ep[2];
        sw += w;
        gc[0]  = fmaf(w, e0.x, gc[0]);  gc[1]  = fmaf(w, e0.y, gc[1]);
        gc[2]  = fmaf(w, e0.z, gc[2]);  gc[3]  = fmaf(w, e0.w, gc[3]);
        gc[4]  = fmaf(w, e1.x, gc[4]);  gc[5]  = fmaf(w, e1.y, gc[5]);
        gc[6]  = fmaf(w, e1.z, gc[6]);  gc[7]  = fmaf(w, e1.w, gc[7]);
        gc[8]  = fmaf(w, e2.x, gc[8]);  gc[9]  = fmaf(w, e2.y, gc[9]);
        gc[10] = fmaf(w, e2.z, gc[10]); gc[11] = fmaf(w, e2.w, gc[11]);
    }
#pragma unroll
    for (int o = 16; o; o >>= 1) {
        sw += __shfl_xor_sync(0xFFFFFFFFu, sw, o);
#pragma unroll
        for (int j = 0; j < DEMB; j++) gc[j] += __shfl_xor_sync(0xFFFFFFFFu, gc[j], o);
    }
    __syncthreads();
    if ((t & 31) == 0) {
        const int w = t >> 5;
#pragma unroll
        for (int j = 0; j < DEMB; j++) red[w][j] = gc[j];
        red[w][12] = sw;
    }
    __syncthreads();
    if (t < 13) {
        float acc = red[0][t];
#pragma unroll
        for (int w = 1; w < 8; w++) acc += red[w][t];
        g_part[blockIdx.x * 13 + t] = acc;
    }
    __threadfence();
    __syncthreads();
    if (t == 0) {
        unsigned done = atomicAdd(&g_done, 1u);
        sh_misc[0] = (done == gridDim.x - 1) ? 1.f : 0.f;
    }
    __syncthreads();
    if (sh_misc[0] == 0.f) return;

    // ---- last block: reduce partials + head MLP ----
    if (t < 13) {
        float acc = 0.f;
        for (int b = 0; b < FIN_GRID; b++) acc += __ldcg(&g_part[b * 13 + t]);
        sh_misc[1 + t] = acc;
    }
    __syncthreads();

    float a = b1[t];
#pragma unroll
    for (int j = 0; j < DEMB; j++) {
        float gj = sh_misc[1 + j] / sh_misc[13];
        a = fmaf(gj, W1[j * DH + t], a);
    }
    h1[t] = fmaxf(a, 0.f);
    __syncthreads();
    if (t < DH) {
        float c = b2[t];
#pragma unroll 8
        for (int k = 0; k < DH; k++) c = fmaf(h1[k], W2[k * DH + t], c);
        h2[t] = fmaxf(c, 0.f);
    }
    __syncthreads();
    if (t < 4) {
        float o = bx[t];
        for (int k = 0; k < DH; k++) o = fmaf(h2[k], Wx[k * 4 + t], o);
        out[t] = o / 10.0f;
    }
    if (t == 4) {
        float o = by[0];
        for (int k = 0; k < DH; k++) o = fmaf(h2[k], Wy[k], o);
        out[4] = o;
    }
}

// ============================================================================
extern "C" void kernel_launch(void* const* d_in, const int* in_sizes, int n_in,
                              void* d_out, int out_size)
{
    const float* nodes  = (const float*)d_in[0];
    const int*   snd    = (const int*)d_in[1];
    const int*   rcv    = (const int*)d_in[2];
    const float* W_enc  = (const float*)d_in[3];
    const float* b_enc  = (const float*)d_in[4];
    const float* W_inf  = (const float*)d_in[5];
    const float* b_inf  = (const float*)d_in[6];
    const float* W_emb  = (const float*)d_in[7];
    const float* b_emb  = (const float*)d_in[8];
    const float* W1     = (const float*)d_in[9];
    const float* b1     = (const float*)d_in[10];
    const float* W2     = (const float*)d_in[11];
    const float* b2     = (const float*)d_in[12];
    const float* Wy     = (const float*)d_in[13];
    const float* by     = (const float*)d_in[14];
    const float* Wx     = (const float*)d_in[15];
    const float* bx     = (const float*)d_in[16];
    float* out = (float*)d_out;

    const int n = in_sizes[0] / FDIM;   // 50000
    const int e = in_sizes[1];          // 1600000

    // A: encode — 128 nodes / block (2 per thread, 4-way column split)
    int blocksA = (n + 127) / 128;
    encode_kernel<<<blocksA, 256>>>(nodes, W_enc, b_enc, W_inf, b_inf, W_emb, b_emb, n);

    // B: persistent scatter + softmax pool + head
    finish_kernel<<<FIN_GRID, 256>>>(snd, rcv, W1, b1, W2, b2, Wy, by, Wx, bx, out, n, e);
}

// round 9
// speedup vs baseline: 1.3134x; 1.0004x over previous
#include <cuda_runtime.h>
#include <cuda_bf16.h>
#include <math_constants.h>

// Problem constants (shapes fixed by the dataset)
#define NN 50000
#define EE 1600000
#define FDIM 128
#define DENC 32
#define DEMB 12
#define NP24 24    // 48 fused output cols (32 enc + 12 emb + 4 pad), 2 per f32x2 pair
#define DH 128
#define FIN_GRID 592   // 4 CTAs/SM x 148 SMs, all co-resident (spin barriers rely on this)

// -------- device scratch (static: no allocation allowed) --------
__device__ float    g_s[NN];            // s[i] = relu(enc[i]) . w_inf[0:32]
__device__ float    g_inf[NN];          // influence logits
__device__ float    g_emb[NN * DEMB];   // emb[i] = nodes[i] @ W_emb + b_emb
__device__ float    g_part[FIN_GRID * 13]; // per-block pooling partials (deterministic)
__device__ unsigned g_bar1, g_bar2, g_done, g_maxu;

// -------- packed f32x2 helpers --------
__device__ __forceinline__ unsigned long long pack2(float lo, float hi) {
    unsigned long long r;
    asm("mov.b64 %0, {%1, %2};" : "=l"(r) : "r"(__float_as_uint(lo)), "r"(__float_as_uint(hi)));
    return r;
}
__device__ __forceinline__ unsigned long long ffma2(unsigned long long a, unsigned long long b,
                                                    unsigned long long c) {
    unsigned long long d;
    asm("fma.rn.f32x2 %0, %1, %2, %3;" : "=l"(d) : "l"(a), "l"(b), "l"(c));
    return d;
}
__device__ __forceinline__ float lo32(unsigned long long v) { return __uint_as_float((unsigned)(v & 0xFFFFFFFFull)); }
__device__ __forceinline__ float hi32(unsigned long long v) { return __uint_as_float((unsigned)(v >> 32)); }

// ordered-float <-> uint for atomicMax
__device__ __forceinline__ unsigned fl_enc(float x) {
    unsigned b = __float_as_uint(x);
    return (b & 0x80000000u) ? ~b : (b | 0x80000000u);
}
__device__ __forceinline__ float fl_dec(unsigned u) {
    unsigned b = (u & 0x80000000u) ? (u ^ 0x80000000u) : ~u;
    return __uint_as_float(b);
}

// ============================================================================
// Kernel A: fused encode. 2 nodes x 6 column-pairs per thread (4-way column
// split). 256 thr/block: colg = tid&3 owns pairs [6*colg, 6*colg+6);
// nsub = tid>>2 picks nodes (base+nsub, base+64+nsub). Biases folded into
// accumulator init.
// ============================================================================
__global__ __launch_bounds__(256) void encode_kernel(
    const float* __restrict__ nodes,
    const float* __restrict__ W_enc,
    const float* __restrict__ b_enc,
    const float* __restrict__ W_inf, const float* __restrict__ b_inf,
    const float* __restrict__ W_emb,
    const float* __restrict__ b_emb,
    int n)
{
    __shared__ __align__(16) unsigned long long Wp[FDIM * NP24]; // [k][jpair]
    __shared__ unsigned long long bpair[NP24];
    __shared__ float sh_winf[33];
    __shared__ float sh_binf;
    __shared__ float s_sh[64 * 8];   // [nsub][node(2)][colg(4)]

    const int tid = threadIdx.x;

    // per-replay reset of finish-kernel state (stream-ordered before finish)
    if (blockIdx.x == 0 && tid < 4) {
        if (tid == 0) g_bar1 = 0u;
        if (tid == 1) g_bar2 = 0u;
        if (tid == 2) g_done = 0u;
        if (tid == 3) g_maxu = 0u;
    }

    for (int idx = tid; idx < FDIM * NP24; idx += 256) {
        int k = idx / NP24, j = idx % NP24;
        int c0 = 2 * j, c1 = 2 * j + 1;
        float w0 = (c0 < DENC) ? W_enc[k * DENC + c0]
                 : (c0 < DENC + DEMB) ? W_emb[k * DEMB + (c0 - DENC)] : 0.f;
        float w1 = (c1 < DENC) ? W_enc[k * DENC + c1]
                 : (c1 < DENC + DEMB) ? W_emb[k * DEMB + (c1 - DENC)] : 0.f;
        Wp[idx] = ((unsigned long long)__float_as_uint(w1) << 32) | __float_as_uint(w0);
    }
    if (tid < NP24) {
        int c0 = 2 * tid, c1 = 2 * tid + 1;
        float v0 = (c0 < DENC) ? b_enc[c0] : (c0 < DENC + DEMB) ? b_emb[c0 - DENC] : 0.f;
        float v1 = (c1 < DENC) ? b_enc[c1] : (c1 < DENC + DEMB) ? b_emb[c1 - DENC] : 0.f;
        bpair[tid] = ((unsigned long long)__float_as_uint(v1) << 32) | __float_as_uint(v0);
    }
    if (tid < 33) sh_winf[tid] = W_inf[tid];
    if (tid == 0) sh_binf = b_inf[0];
    __syncthreads();

    const int colg = tid & 3;
    const int nsub = tid >> 2;
    const int base = blockIdx.x * 128;
    const int i0 = base + nsub;
    const int i1 = base + 64 + nsub;
    const bool v0 = (i0 < n), v1 = (i1 < n);
    const float4* r0 = (const float4*)(nodes + (v0 ? (size_t)i0 * FDIM : 0));
    const float4* r1 = (const float4*)(nodes + (v1 ? (size_t)i1 * FDIM : 0));
    const int jg = 6 * colg;

    unsigned long long acc0[6], acc1[6];
#pragma unroll
    for (int p = 0; p < 6; p++) { acc0[p] = bpair[jg + p]; acc1[p] = bpair[jg + p]; }

    float4 a0 = r0[0], a1 = r1[0];
    float last0 = 0.f, last1 = 0.f;
#pragma unroll 1
    for (int c = 0; c < FDIM / 4; c++) {
        float4 p0, p1;
        if (c < FDIM / 4 - 1) { p0 = r0[c + 1]; p1 = r1[c + 1]; }
#pragma unroll
        for (int q = 0; q < 4; q++) {
            float f0 = (q == 0) ? a0.x : (q == 1) ? a0.y : (q == 2) ? a0.z : a0.w;
            float f1 = (q == 0) ? a1.x : (q == 1) ? a1.y : (q == 2) ? a1.z : a1.w;
            unsigned long long x0 = pack2(f0, f0);
            unsigned long long x1 = pack2(f1, f1);
            const ulonglong2* w2 = (const ulonglong2*)&Wp[(4 * c + q) * NP24 + jg];
            ulonglong2 wa = w2[0], wb = w2[1], wc = w2[2];
            acc0[0] = ffma2(x0, wa.x, acc0[0]); acc1[0] = ffma2(x1, wa.x, acc1[0]);
            acc0[1] = ffma2(x0, wa.y, acc0[1]); acc1[1] = ffma2(x1, wa.y, acc1[1]);
            acc0[2] = ffma2(x0, wb.x, acc0[2]); acc1[2] = ffma2(x1, wb.x, acc1[2]);
            acc0[3] = ffma2(x0, wb.y, acc0[3]); acc1[3] = ffma2(x1, wb.y, acc1[3]);
            acc0[4] = ffma2(x0, wc.x, acc0[4]); acc1[4] = ffma2(x1, wc.x, acc1[4]);
            acc0[5] = ffma2(x0, wc.y, acc0[5]); acc1[5] = ffma2(x1, wc.y, acc1[5]);
        }
        if (c == FDIM / 4 - 1) { last0 = a0.w; last1 = a1.w; }
        a0 = p0; a1 = p1;
    }

    // partial s over enc pairs (j < 16); bias already in acc
    float s0 = 0.f, s1 = 0.f;
#pragma unroll
    for (int p = 0; p < 6; p++) {
        int j = jg + p;
        if (j < 16) {
            float wl = sh_winf[2 * j], wh = sh_winf[2 * j + 1];
            s0 = fmaf(fmaxf(lo32(acc0[p]), 0.f), wl, s0);
            s0 = fmaf(fmaxf(hi32(acc0[p]), 0.f), wh, s0);
            s1 = fmaf(fmaxf(lo32(acc1[p]), 0.f), wl, s1);
            s1 = fmaf(fmaxf(hi32(acc1[p]), 0.f), wh, s1);
        }
    }
    s_sh[nsub * 8 + colg]     = s0;
    s_sh[nsub * 8 + 4 + colg] = s1;
    __syncthreads();

    if (colg == 0 && v0) {
        float s = s_sh[nsub * 8 + 0] + s_sh[nsub * 8 + 1] + s_sh[nsub * 8 + 2] + s_sh[nsub * 8 + 3];
        g_s[i0] = s;
        g_inf[i0] = s + last0 * sh_winf[32] + sh_binf;
    }
    if (colg == 1 && v1) {
        float s = s_sh[nsub * 8 + 4] + s_sh[nsub * 8 + 5] + s_sh[nsub * 8 + 6] + s_sh[nsub * 8 + 7];
        g_s[i1] = s;
        g_inf[i1] = s + last1 * sh_winf[32] + sh_binf;
    }
    // emb: colg2 holds pairs j16,j17 (emb cols 0-3); colg3 holds j18..21 (cols 4-11)
    if (colg == 2) {
        float4 u; u.x = lo32(acc0[4]); u.y = hi32(acc0[4]); u.z = lo32(acc0[5]); u.w = hi32(acc0[5]);
        if (v0) ((float4*)(g_emb + (size_t)i0 * DEMB))[0] = u;
        u.x = lo32(acc1[4]); u.y = hi32(acc1[4]); u.z = lo32(acc1[5]); u.w = hi32(acc1[5]);
        if (v1) ((float4*)(g_emb + (size_t)i1 * DEMB))[0] = u;
    }
    if (colg == 3) {
        float4 u;
        if (v0) {
            float4* ep = (float4*)(g_emb + (size_t)i0 * DEMB);
            u.x = lo32(acc0[0]); u.y = hi32(acc0[0]); u.z = lo32(acc0[1]); u.w = hi32(acc0[1]); ep[1] = u;
            u.x = lo32(acc0[2]); u.y = hi32(acc0[2]); u.z = lo32(acc0[3]); u.w = hi32(acc0[3]); ep[2] = u;
        }
        if (v1) {
            float4* ep = (float4*)(g_emb + (size_t)i1 * DEMB);
            u.x = lo32(acc1[0]); u.y = hi32(acc1[0]); u.z = lo32(acc1[1]); u.w = hi32(acc1[1]); ep[1] = u;
            u.x = lo32(acc1[2]); u.y = hi32(acc1[2]); u.z = lo32(acc1[3]); u.w = hi32(acc1[3]); ep[2] = u;
        }
    }
}

// ============================================================================
// Kernel B: persistent fused finish. grid = 592 (4 CTAs/SM, all co-resident):
//   phase 1: edge scatter inf[recv] += s[snd]  (8 edges/iter for MLP)
//   spin barrier 1
//   phase 2: global max of inf (atomicMax on ordered-uint)
//   spin barrier 2
//   phase 3: float softmax pooling -> deterministic per-block partials
//   last block: sum partials + head MLP
// ============================================================================
__global__ __launch_bounds__(256, 4) void finish_kernel(
    const int* __restrict__ snd, const int* __restrict__ rcv,
    const float* __restrict__ W1, const float* __restrict__ b1,
    const float* __restrict__ W2, const float* __restrict__ b2,
    const float* __restrict__ Wy, const float* __restrict__ by,
    const float* __restrict__ Wx, const float* __restrict__ bx,
    float* __restrict__ out, int n, int e)
{
    __shared__ float red[8][13];
    __shared__ float sh_misc[16];   // [0]=last-block flag; [1..13]=summed accum
    __shared__ float h1[DH], h2[DH];

    const int t = threadIdx.x;
    const int gtid = blockIdx.x * 256 + t;
    const int gstride = gridDim.x * 256;

    // ---- phase 1: scatter, 8 edges per iteration ----
    const int no = e >> 3;   // octets
    for (int q = gtid; q < no; q += gstride) {
        int4 sa = ((const int4*)snd)[2 * q];
        int4 sb = ((const int4*)snd)[2 * q + 1];
        int4 ra = ((const int4*)rcv)[2 * q];
        int4 rb = ((const int4*)rcv)[2 * q + 1];
        float v0 = __ldg(&g_s[sa.x]);
        float v1 = __ldg(&g_s[sa.y]);
        float v2 = __ldg(&g_s[sa.z]);
        float v3 = __ldg(&g_s[sa.w]);
        float v4 = __ldg(&g_s[sb.x]);
        float v5 = __ldg(&g_s[sb.y]);
        float v6 = __ldg(&g_s[sb.z]);
        float v7 = __ldg(&g_s[sb.w]);
        atomicAdd(&g_inf[ra.x], v0);
        atomicAdd(&g_inf[ra.y], v1);
        atomicAdd(&g_inf[ra.z], v2);
        atomicAdd(&g_inf[ra.w], v3);
        atomicAdd(&g_inf[rb.x], v4);
        atomicAdd(&g_inf[rb.y], v5);
        atomicAdd(&g_inf[rb.z], v6);
        atomicAdd(&g_inf[rb.w], v7);
    }
    for (int i = (no << 3) + gtid; i < e; i += gstride)
        atomicAdd(&g_inf[rcv[i]], __ldg(&g_s[snd[i]]));

    __threadfence();
    if (t == 0) {
        atomicAdd(&g_bar1, 1u);
        while (*(volatile unsigned*)&g_bar1 < gridDim.x) { }
    }
    __syncthreads();

    // ---- phase 2: max ----
    float m = -CUDART_INF_F;
    for (int i = gtid; i < n; i += gstride) m = fmaxf(m, __ldcg(&g_inf[i]));
#pragma unroll
    for (int o = 16; o; o >>= 1) m = fmaxf(m, __shfl_xor_sync(0xFFFFFFFFu, m, o));
    if ((t & 31) == 0) red[t >> 5][0] = m;
    __syncthreads();
    if (t == 0) {
        float mm = red[0][0];
        for (int w = 1; w < 8; w++) mm = fmaxf(mm, red[w][0]);
        atomicMax(&g_maxu, fl_enc(mm));
        __threadfence();
        atomicAdd(&g_bar2, 1u);
        while (*(volatile unsigned*)&g_bar2 < gridDim.x) { }
        sh_misc[15] = fl_dec(*(volatile unsigned*)&g_maxu);
    }
    __syncthreads();
    const float gm = sh_misc[15];

    // ---- phase 3: float softmax pooling ----
    float sw = 0.f;
    float gc[DEMB];
#pragma unroll
    for (int j = 0; j < DEMB; j++) gc[j] = 0.f;
    for (int i = gtid; i < n; i += gstride) {
        float w = __expf(__ldcg(&g_inf[i]) - gm);
        const float4* ep = (const float4*)(g_emb + (size_t)i * DEMB);
        float4 e0 = ep[0], e1 = ep[1], e2 = ep[2];
        sw += w;
        gc[0]  = fmaf(w, e0.x, gc[0]);  gc[1]  = fmaf(w, e0.y, gc[1]);
        gc[2]  = fmaf(w, e0.z, gc[2]);  gc[3]  = fmaf(w, e0.w, gc[3]);
        gc[4]  = fmaf(w, e1.x, gc[4]);  gc[5]  = fmaf(w, e1.y, gc[5]);
        gc[6]  = fmaf(w, e1.z, gc[6]);  gc[7]  = fmaf(w, e1.w, gc[7]);
        gc[8]  = fmaf(w, e2.x, gc[8]);  gc[9]  = fmaf(w, e2.y, gc[9]);
        gc[10] = fmaf(w, e2.z, gc[10]); gc[11] = fmaf(w, e2.w, gc[11]);
    }
#pragma unroll
    for (int o = 16; o; o >>= 1) {
        sw += __shfl_xor_sync(0xFFFFFFFFu, sw, o);
#pragma unroll
        for (int j = 0; j < DEMB; j++) gc[j] += __shfl_xor_sync(0xFFFFFFFFu, gc[j], o);
    }
    __syncthreads();
    if ((t & 31) == 0) {
        const int w = t >> 5;
#pragma unroll
        for (int j = 0; j < DEMB; j++) red[w][j] = gc[j];
        red[w][12] = sw;
    }
    __syncthreads();
    if (t < 13) {
        float acc = red[0][t];
#pragma unroll
        for (int w = 1; w < 8; w++) acc += red[w][t];
        g_part[blockIdx.x * 13 + t] = acc;
    }
    __threadfence();
    __syncthreads();
    if (t == 0) {
        unsigned done = atomicAdd(&g_done, 1u);
        sh_misc[0] = (done == gridDim.x - 1) ? 1.f : 0.f;
    }
    __syncthreads();
    if (sh_misc[0] == 0.f) return;

    // ---- last block: reduce partials (all 256 threads) + head MLP ----
    {
        float pacc[13];
#pragma unroll
        for (int j = 0; j < 13; j++) pacc[j] = 0.f;
        for (int b = t; b < FIN_GRID; b += 256) {
#pragma unroll
            for (int j = 0; j < 13; j++) pacc[j] += __ldcg(&g_part[b * 13 + j]);
        }
#pragma unroll
        for (int o = 16; o; o >>= 1)
#pragma unroll
            for (int j = 0; j < 13; j++) pacc[j] += __shfl_xor_sync(0xFFFFFFFFu, pacc[j], o);
        __syncthreads();
        if ((t & 31) == 0) {
            const int w = t >> 5;
#pragma unroll
            for (int j = 0; j < 13; j++) red[w][j] = pacc[j];
        }
        __syncthreads();
        if (t < 13) {
            float acc = red[0][t];
#pragma unroll
            for (int w = 1; w < 8; w++) acc += red[w][t];
            sh_misc[1 + t] = acc;
        }
        __syncthreads();
    }

    float a = b1[t];
#pragma unroll
    for (int j = 0; j < DEMB; j++) {
        float gj = sh_misc[1 + j] / sh_misc[13];
        a = fmaf(gj, W1[j * DH + t], a);
    }
    h1[t] = fmaxf(a, 0.f);
    __syncthreads();
    if (t < DH) {
        float c = b2[t];
#pragma unroll 8
        for (int k = 0; k < DH; k++) c = fmaf(h1[k], W2[k * DH + t], c);
        h2[t] = fmaxf(c, 0.f);
    }
    __syncthreads();
    if (t < 4) {
        float o = bx[t];
        for (int k = 0; k < DH; k++) o = fmaf(h2[k], Wx[k * 4 + t], o);
        out[t] = o / 10.0f;
    }
    if (t == 4) {
        float o = by[0];
        for (int k = 0; k < DH; k++) o = fmaf(h2[k], Wy[k], o);
        out[4] = o;
    }
}

// ============================================================================
extern "C" void kernel_launch(void* const* d_in, const int* in_sizes, int n_in,
                              void* d_out, int out_size)
{
    const float* nodes  = (const float*)d_in[0];
    const int*   snd    = (const int*)d_in[1];
    const int*   rcv    = (const int*)d_in[2];
    const float* W_enc  = (const float*)d_in[3];
    const float* b_enc  = (const float*)d_in[4];
    const float* W_inf  = (const float*)d_in[5];
    const float* b_inf  = (const float*)d_in[6];
    const float* W_emb  = (const float*)d_in[7];
    const float* b_emb  = (const float*)d_in[8];
    const float* W1     = (const float*)d_in[9];
    const float* b1     = (const float*)d_in[10];
    const float* W2     = (const float*)d_in[11];
    const float* b2     = (const float*)d_in[12];
    const float* Wy     = (const float*)d_in[13];
    const float* by     = (const float*)d_in[14];
    const float* Wx     = (const float*)d_in[15];
    const float* bx     = (const float*)d_in[16];
    float* out = (float*)d_out;

    const int n = in_sizes[0] / FDIM;   // 50000
    const int e = in_sizes[1];          // 1600000

    // A: encode — 128 nodes / block (2 per thread, 4-way column split)
    int blocksA = (n + 127) / 128;
    encode_kernel<<<blocksA, 256>>>(nodes, W_enc, b_enc, W_inf, b_inf, W_emb, b_emb, n);

    // B: persistent scatter + softmax pool + head (4 CTAs/SM co-resident)
    finish_kernel<<<FIN_GRID, 256>>>(snd, rcv, W1, b1, W2, b2, Wy, by, Wx, bx, out, n, e);
}